// round 15
// baseline (speedup 1.0000x reference)
#include <cuda_runtime.h>
#include <cuda_fp16.h>
#include <math.h>
#include <stdint.h>

// ---------------------------------------------------------------------------
// MMD^2 (RBF, gamma=1), 8192x16 fp32, via mma.sync.m16n8k16 fp16 (sm_100 base).
//
// Coords scaled by sqrt(2*log2e), split x = hi + lo (fp16) ONCE in
// split_kernel. K = 48: A chunks [hi | lo | hi], B chunks [hi | hi | lo]
//   => acc = 2*log2e*dot(a,b)  (lo*lo dropped, ~2^-22 rel)
// Epilogue: k = ex2(acc) * ena * enb, ena/enb = exp2(-0.5|x_s|^2) per row.
// CTA = 256 threads, output tile 128x128, warp tile 32m x 64n (L1-optimal,
// the validated R10 shape). Upper-triangle tiles, weight 2 off-diagonal.
// Final fixed-order reduction fused into the last pair CTA
// (threadfence-reduction pattern; counter reset by split_kernel).
// ---------------------------------------------------------------------------

#define NSRC   8192
#define D      16
#define NP     16384
#define TILE   128
#define TB     (NP / TILE)                 // 128
#define NBLK   (TB * (TB + 1) / 2)         // 8256 triangle tiles
#define SQ2L   1.6986436004918308f         // sqrt(2*log2(e))
#define ROWB   112                         // 96B data + 16B pad (conflict-free)
#define NKC    3                           // K = 48, chunks of 16
#define ATILEB (TILE * ROWB)               // 14336 B per tile side

// per point: u0,u1 = hi(16 fp16), u2,u3 = lo
__device__ uint4  g_S[NP * 4];
__device__ float  g_N[NP];                 // -0.5*|x_s|^2
__device__ double g_part[NBLK];
__device__ unsigned int g_count;

// ---------------- helpers ----------------
__device__ __forceinline__ float ex2(float x) {
    float r; asm("ex2.approx.f32 %0, %1;" : "=f"(r) : "f"(x)); return r;
}
__device__ __forceinline__ uint32_t smem_u32(const void* p) {
    uint32_t a;
    asm("{ .reg .u64 t; cvta.to.shared.u64 t, %1; cvt.u32.u64 %0, t; }"
        : "=r"(a) : "l"(p));
    return a;
}
__device__ __forceinline__ void ldsm4(uint32_t* r, uint32_t addr) {
    asm volatile("ldmatrix.sync.aligned.m8n8.x4.shared.b16 {%0,%1,%2,%3}, [%4];"
                 : "=r"(r[0]), "=r"(r[1]), "=r"(r[2]), "=r"(r[3]) : "r"(addr));
}
__device__ __forceinline__ void mma16816(float* c, const uint32_t* a,
                                         uint32_t b0, uint32_t b1) {
    asm volatile("mma.sync.aligned.m16n8k16.row.col.f32.f16.f16.f32 "
                 "{%0,%1,%2,%3}, {%4,%5,%6,%7}, {%8,%9}, {%0,%1,%2,%3};"
                 : "+f"(c[0]), "+f"(c[1]), "+f"(c[2]), "+f"(c[3])
                 : "r"(a[0]), "r"(a[1]), "r"(a[2]), "r"(a[3]), "r"(b0), "r"(b1));
}
__device__ __forceinline__ int tri_row_start(int t) {
    return t * TB - ((t * (t - 1)) >> 1);
}

// ---------------------------------------------------------------------------
// Kernel 1: scale, fp16 hi/lo split, norm term. Also resets g_count.
// ---------------------------------------------------------------------------
__global__ void __launch_bounds__(128) split_kernel(const float* __restrict__ src,
                                                    const float* __restrict__ tgt) {
    if (blockIdx.x == 0 && threadIdx.x == 0) g_count = 0u;
    int p = blockIdx.x * 128 + threadIdx.x;
    if (p >= NP) return;
    const float* x = (p < NSRC) ? (src + (size_t)p * D) : (tgt + (size_t)(p - NSRC) * D);

    uint4 u[4];
    __half* hi = (__half*)&u[0];
    __half* lo = (__half*)&u[2];

    float ns = 0.f;
#pragma unroll
    for (int d = 0; d < D; d++) {
        float v = x[d] * SQ2L;
        ns = fmaf(v, v, ns);
        __half h = __float2half_rn(v);
        hi[d] = h;
        lo[d] = __float2half_rn(v - __half2float(h));
    }
    uint4* out = g_S + (size_t)p * 4;
#pragma unroll
    for (int i = 0; i < 4; i++) out[i] = u[i];
    g_N[p] = -0.5f * ns;
}

// ---------------------------------------------------------------------------
// Kernel 2: pairwise 128x128 tiles via fp16 mma.sync (K=48), epilogue norms,
// fused last-CTA final reduction.
// Warp w: rows (w&3)*32 + {0,16}, cols (w>>2)*64 (8 n8-tiles).
// ---------------------------------------------------------------------------
__global__ void __launch_bounds__(256, 2) pair_kernel(float* __restrict__ out) {
    extern __shared__ __align__(16) char dsm[];
    __shared__ float  sLA[TILE];
    __shared__ float  sLB[TILE];
    __shared__ float  wsum[8];
    __shared__ double sred[256];
    __shared__ unsigned int s_rank;

    const int bid  = blockIdx.x;
    const int tid  = threadIdx.x;
    const int lane = tid & 31;
    const int w    = tid >> 5;

    int ti = (int)((2.0 * TB + 1.0 - sqrt((2.0 * TB + 1.0) * (2.0 * TB + 1.0)
                                          - 8.0 * (double)bid)) * 0.5);
    while (tri_row_start(ti + 1) <= bid) ti++;
    while (tri_row_start(ti) > bid) ti--;
    const int tj = ti + (bid - tri_row_start(ti));

    // ---- build A/B tiles in SMEM (row stride 112B; conflict-free ldmatrix) ----
    {
        const int  row = tid & 127;
        const bool isA = tid < 128;
        const int  pt  = (isA ? ti : tj) * TILE + row;
        const uint4* srow = g_S + (size_t)pt * 4;
        char* rbase = dsm + (isA ? 0 : ATILEB) + row * ROWB;

        uint4 u[4];
#pragma unroll
        for (int i = 0; i < 4; i++) u[i] = srow[i];

        // A: [hi hi lo lo hi hi]    B: [hi hi hi hi lo lo]
        const int mapA[6] = {0,1, 2,3, 0,1};
        const int mapB[6] = {0,1, 0,1, 2,3};
#pragma unroll
        for (int c = 0; c < 6; c++) {
            int s = isA ? mapA[c] : mapB[c];
            *(uint4*)(rbase + c * 16) = u[s];
        }
        float e = ex2(g_N[pt]);
        if (isA) sLA[row] = e; else sLB[row] = e;
    }
    __syncthreads();

    const uint32_t sA = smem_u32(dsm);
    const uint32_t sB = sA + ATILEB;
    const int mbase = (w & 3) * 32;
    const int nbase = (w >> 2) * 64;
    const int gid = lane >> 2;
    const int tig = lane & 3;

    // ---- preload A fragments (3 kc x 2 m-tiles = 24 regs) ----
    const uint32_t aRow   = (uint32_t)(mbase + (lane & 7) + ((lane >> 3) & 1) * 8);
    const uint32_t aAddr0 = sA + aRow * ROWB + ((lane >> 4) & 1) * 16;
    const uint32_t aAddr1 = aAddr0 + 16 * ROWB;
    uint32_t a0[NKC][4], a1[NKC][4];
#pragma unroll
    for (int kc = 0; kc < NKC; kc++) {
        ldsm4(a0[kc], aAddr0 + kc * 32);
        ldsm4(a1[kc], aAddr1 + kc * 32);
    }

    const uint32_t bRowQ = (uint32_t)((lane & 7) + ((lane >> 4) & 1) * 8);
    const uint32_t bColH = ((lane >> 3) & 1) * 16;
    uint32_t bAddr[4];
#pragma unroll
    for (int q = 0; q < 4; q++)
        bAddr[q] = sB + (uint32_t)(nbase + 16 * q + bRowQ) * ROWB + bColH;

    float acc[2][8][4];
#pragma unroll
    for (int mt = 0; mt < 2; mt++)
#pragma unroll
        for (int nt = 0; nt < 8; nt++)
#pragma unroll
            for (int e = 0; e < 4; e++) acc[mt][nt][e] = 0.f;

#pragma unroll
    for (int kc = 0; kc < NKC; kc++) {
        const uint32_t ko = kc * 32;
        uint32_t b[4][4];
#pragma unroll
        for (int q = 0; q < 4; q++) ldsm4(b[q], bAddr[q] + ko);
#pragma unroll
        for (int nt = 0; nt < 8; nt++) {
            const uint32_t b0 = b[nt >> 1][(nt & 1) * 2];
            const uint32_t b1 = b[nt >> 1][(nt & 1) * 2 + 1];
            mma16816(acc[0][nt], a0[kc], b0, b1);
            mma16816(acc[1][nt], a1[kc], b0, b1);
        }
    }

    // ---- epilogue: k = ex2(acc) * ena * enb; sum over tile ----
    float ena[2][2];
#pragma unroll
    for (int mt = 0; mt < 2; mt++)
#pragma unroll
        for (int h = 0; h < 2; h++)
            ena[mt][h] = sLA[mbase + mt * 16 + gid + h * 8];

    float enb[8][2];
#pragma unroll
    for (int nt = 0; nt < 8; nt++) {
        int j0 = nbase + nt * 8 + tig * 2;
        enb[nt][0] = sLB[j0];
        enb[nt][1] = sLB[j0 + 1];
    }

    float p[2][2] = {{0.f, 0.f}, {0.f, 0.f}};
#pragma unroll
    for (int mt = 0; mt < 2; mt++)
#pragma unroll
        for (int nt = 0; nt < 8; nt++)
#pragma unroll
            for (int e = 0; e < 4; e++)
                p[mt][e >> 1] = fmaf(ex2(acc[mt][nt][e]), enb[nt][e & 1],
                                     p[mt][e >> 1]);

    float tsum = 0.f;
#pragma unroll
    for (int mt = 0; mt < 2; mt++)
#pragma unroll
        for (int h = 0; h < 2; h++)
            tsum = fmaf(p[mt][h], ena[mt][h], tsum);

#pragma unroll
    for (int off = 16; off; off >>= 1)
        tsum += __shfl_xor_sync(0xffffffffu, tsum, off);
    if (lane == 0) wsum[w] = tsum;
    __syncthreads();

    if (tid == 0) {
        double t = 0.0;
#pragma unroll
        for (int x = 0; x < 8; x++) t += (double)wsum[x];
        double wgt = (ti == tj) ? 1.0 : 2.0;
        double sgn = ((ti < TB / 2) == (tj < TB / 2)) ? 1.0 : -1.0;
        g_part[bid] = t * wgt * sgn;
        __threadfence();
        s_rank = atomicAdd(&g_count, 1u);
    }
    __syncthreads();

    // ---- last CTA: deterministic fixed-order final reduction ----
    if (s_rank == NBLK - 1) {
        const volatile double* gp = g_part;
        double t = 0.0;
        for (int i = tid; i < NBLK; i += 256) t += gp[i];
        sred[tid] = t;
        __syncthreads();
#pragma unroll
        for (int off = 128; off; off >>= 1) {
            if (tid < off) sred[tid] += sred[tid + off];
            __syncthreads();
        }
        if (tid == 0) out[0] = (float)(sred[0] / 67108864.0);   // / n^2
    }
}

// ---------------------------------------------------------------------------
extern "C" void kernel_launch(void* const* d_in, const int* in_sizes, int n_in,
                              void* d_out, int out_size) {
    const float* src = (const float*)d_in[0];
    const float* tgt = (const float*)d_in[1];

    const int smem_bytes = 2 * ATILEB;     // 28672 B
    cudaFuncSetAttribute(pair_kernel, cudaFuncAttributeMaxDynamicSharedMemorySize,
                         smem_bytes);

    split_kernel<<<NP / 128, 128>>>(src, tgt);
    pair_kernel<<<NBLK, 256, smem_bytes>>>((float*)d_out);
}

// round 16
// speedup vs baseline: 1.4036x; 1.4036x over previous
#include <cuda_runtime.h>
#include <cuda_fp16.h>
#include <math.h>
#include <stdint.h>

// ---------------------------------------------------------------------------
// MMD^2 (RBF, gamma=1), 8192x16 fp32, via mma.sync.m16n8k16 fp16 (sm_100 base).
//
// Coords scaled by sqrt(2*log2e), split x = hi + lo (fp16) once in
// split_kernel. K = 48: A chunks [hi | lo | hi], B chunks [hi | hi | lo]
//   => acc = 2*log2e*dot(a,b)  (lo*lo dropped, ~2^-22 rel)
// Epilogue: k = ex2(acc) * ena * enb, ena/enb = exp2(-0.5|x_s|^2) per row.
// Each CTA (256 thr) computes a 128m x 256n super-tile: two 128x128 tiles
// (ti, 2c) and (ti, 2c+1) sharing one A tile + A fragments. Warp tile
// 32m x 64n (the validated L1-optimal shape). Upper triangle only.
// ---------------------------------------------------------------------------

#define NSRC   8192
#define D      16
#define NP     16384
#define TILE   128
#define TB     (NP / TILE)                 // 128
#define NCJ    (TB / 2)                    // 64 column pairs
#define NBLK2  (NCJ * TB)                  // 8192 CTAs
#define SQ2L   1.6986436004918308f         // sqrt(2*log2(e))
#define ROWB   112                         // 96B data + 16B pad (conflict-free)
#define NKC    3                           // K = 48, chunks of 16
#define ATILEB (TILE * ROWB)               // 14336 B per 128-row tile

// per point: u0,u1 = hi(16 fp16), u2,u3 = lo
__device__ uint4  g_S[NP * 4];
__device__ float  g_N[NP];                 // -0.5*|x_s|^2
__device__ double g_part[NBLK2];

// ---------------- helpers ----------------
__device__ __forceinline__ float ex2(float x) {
    float r; asm("ex2.approx.f32 %0, %1;" : "=f"(r) : "f"(x)); return r;
}
__device__ __forceinline__ uint32_t smem_u32(const void* p) {
    uint32_t a;
    asm("{ .reg .u64 t; cvta.to.shared.u64 t, %1; cvt.u32.u64 %0, t; }"
        : "=r"(a) : "l"(p));
    return a;
}
__device__ __forceinline__ void ldsm4(uint32_t* r, uint32_t addr) {
    asm volatile("ldmatrix.sync.aligned.m8n8.x4.shared.b16 {%0,%1,%2,%3}, [%4];"
                 : "=r"(r[0]), "=r"(r[1]), "=r"(r[2]), "=r"(r[3]) : "r"(addr));
}
__device__ __forceinline__ void mma16816(float* c, const uint32_t* a,
                                         uint32_t b0, uint32_t b1) {
    asm volatile("mma.sync.aligned.m16n8k16.row.col.f32.f16.f16.f32 "
                 "{%0,%1,%2,%3}, {%4,%5,%6,%7}, {%8,%9}, {%0,%1,%2,%3};"
                 : "+f"(c[0]), "+f"(c[1]), "+f"(c[2]), "+f"(c[3])
                 : "r"(a[0]), "r"(a[1]), "r"(a[2]), "r"(a[3]), "r"(b0), "r"(b1));
}

// ---------------------------------------------------------------------------
// Kernel 1: scale, fp16 hi/lo split, norm term.
// ---------------------------------------------------------------------------
__global__ void __launch_bounds__(128) split_kernel(const float* __restrict__ src,
                                                    const float* __restrict__ tgt) {
    int p = blockIdx.x * 128 + threadIdx.x;
    if (p >= NP) return;
    const float* x = (p < NSRC) ? (src + (size_t)p * D) : (tgt + (size_t)(p - NSRC) * D);

    uint4 u[4];
    __half* hi = (__half*)&u[0];
    __half* lo = (__half*)&u[2];

    float ns = 0.f;
#pragma unroll
    for (int d = 0; d < D; d++) {
        float v = x[d] * SQ2L;
        ns = fmaf(v, v, ns);
        __half h = __float2half_rn(v);
        hi[d] = h;
        lo[d] = __float2half_rn(v - __half2float(h));
    }
    uint4* out = g_S + (size_t)p * 4;
#pragma unroll
    for (int i = 0; i < 4; i++) out[i] = u[i];
    g_N[p] = -0.5f * ns;
}

// ---------------------------------------------------------------------------
// Kernel 2: 128x256 super-tile per CTA (two 128x128 tiles sharing A).
// blockIdx = (c, ti); tj0 = 2c, tj1 = 2c+1; skip halves with tj < ti.
// Warp w: rows (w&3)*32 + {0,16}, cols (w>>2)*64 within each half.
// ---------------------------------------------------------------------------
__global__ void __launch_bounds__(256, 2) pair_kernel() {
    extern __shared__ __align__(16) char dsm[];
    __shared__ float sLA[TILE];
    __shared__ float sLB[2 * TILE];
    __shared__ float wsum[2][8];

    const int tid  = threadIdx.x;
    const int lane = tid & 31;
    const int w    = tid >> 5;

    const int ti  = blockIdx.y;
    const int tj0 = 2 * blockIdx.x;
    const int tj1 = tj0 + 1;
    const int bid = blockIdx.y * NCJ + blockIdx.x;

    if (tj1 < ti) {                       // both halves below diagonal
        if (tid == 0) g_part[bid] = 0.0;
        return;
    }
    const bool act0 = (tj0 >= ti);        // act1 always true here

    // ---- build A (rows 0..127), B0 (128..255), B1 (256..383) ----
    for (int r = tid; r < 384; r += 256) {
        const int grp = r >> 7;           // 0=A, 1=B0, 2=B1
        const int row = r & 127;
        if (grp == 1 && !act0) continue;
        const int tt = (grp == 0) ? ti : ((grp == 1) ? tj0 : tj1);
        const int pt = tt * TILE + row;
        const uint4* srow = g_S + (size_t)pt * 4;
        char* rbase = dsm + grp * ATILEB + row * ROWB;

        uint4 u[4];
#pragma unroll
        for (int i = 0; i < 4; i++) u[i] = srow[i];

        // A: [hi hi lo lo hi hi]    B: [hi hi hi hi lo lo]
        const int mapA[6] = {0,1, 2,3, 0,1};
        const int mapB[6] = {0,1, 0,1, 2,3};
#pragma unroll
        for (int c = 0; c < 6; c++) {
            int s = (grp == 0) ? mapA[c] : mapB[c];
            *(uint4*)(rbase + c * 16) = u[s];
        }
        float e = ex2(g_N[pt]);
        if (grp == 0) sLA[row] = e;
        else          sLB[(grp - 1) * TILE + row] = e;
    }
    __syncthreads();

    const uint32_t sA = smem_u32(dsm);
    const int mbase = (w & 3) * 32;
    const int nbase = (w >> 2) * 64;
    const int gid = lane >> 2;
    const int tig = lane & 3;

    // ---- preload A fragments ONCE (3 kc x 2 m-tiles = 24 regs) ----
    const uint32_t aRow   = (uint32_t)(mbase + (lane & 7) + ((lane >> 3) & 1) * 8);
    const uint32_t aAddr0 = sA + aRow * ROWB + ((lane >> 4) & 1) * 16;
    const uint32_t aAddr1 = aAddr0 + 16 * ROWB;
    uint32_t a0[NKC][4], a1[NKC][4];
#pragma unroll
    for (int kc = 0; kc < NKC; kc++) {
        ldsm4(a0[kc], aAddr0 + kc * 32);
        ldsm4(a1[kc], aAddr1 + kc * 32);
    }

    float ena[2][2];
#pragma unroll
    for (int mt = 0; mt < 2; mt++)
#pragma unroll
        for (int h = 0; h < 2; h++)
            ena[mt][h] = sLA[mbase + mt * 16 + gid + h * 8];

    const uint32_t bRowQ = (uint32_t)((lane & 7) + ((lane >> 4) & 1) * 8);
    const uint32_t bColH = ((lane >> 3) & 1) * 16;

    // ================= two sequential halves =================
#pragma unroll 1
    for (int half = 0; half < 2; half++) {
        if (half == 0 && !act0) {
            if (lane == 0) wsum[0][w] = 0.f;
            continue;
        }
        const uint32_t sB = sA + (1 + half) * ATILEB;
        uint32_t bAddr[4];
#pragma unroll
        for (int q = 0; q < 4; q++)
            bAddr[q] = sB + (uint32_t)(nbase + 16 * q + bRowQ) * ROWB + bColH;

        float acc[2][8][4];
#pragma unroll
        for (int mt = 0; mt < 2; mt++)
#pragma unroll
            for (int nt = 0; nt < 8; nt++)
#pragma unroll
                for (int e = 0; e < 4; e++) acc[mt][nt][e] = 0.f;

#pragma unroll
        for (int kc = 0; kc < NKC; kc++) {
            const uint32_t ko = kc * 32;
            uint32_t b[4][4];
#pragma unroll
            for (int q = 0; q < 4; q++) ldsm4(b[q], bAddr[q] + ko);
#pragma unroll
            for (int nt = 0; nt < 8; nt++) {
                const uint32_t b0 = b[nt >> 1][(nt & 1) * 2];
                const uint32_t b1 = b[nt >> 1][(nt & 1) * 2 + 1];
                mma16816(acc[0][nt], a0[kc], b0, b1);
                mma16816(acc[1][nt], a1[kc], b0, b1);
            }
        }

        // ---- epilogue: k = ex2(acc) * ena * enb ----
        const float* lb = sLB + half * TILE;
        float enb[8][2];
#pragma unroll
        for (int nt = 0; nt < 8; nt++) {
            int j0 = nbase + nt * 8 + tig * 2;
            enb[nt][0] = lb[j0];
            enb[nt][1] = lb[j0 + 1];
        }

        float p[2][2] = {{0.f, 0.f}, {0.f, 0.f}};
#pragma unroll
        for (int mt = 0; mt < 2; mt++)
#pragma unroll
            for (int nt = 0; nt < 8; nt++)
#pragma unroll
                for (int e = 0; e < 4; e++)
                    p[mt][e >> 1] = fmaf(ex2(acc[mt][nt][e]), enb[nt][e & 1],
                                         p[mt][e >> 1]);

        float tsum = 0.f;
#pragma unroll
        for (int mt = 0; mt < 2; mt++)
#pragma unroll
            for (int h = 0; h < 2; h++)
                tsum = fmaf(p[mt][h], ena[mt][h], tsum);

#pragma unroll
        for (int off = 16; off; off >>= 1)
            tsum += __shfl_xor_sync(0xffffffffu, tsum, off);
        if (lane == 0) wsum[half][w] = tsum;
    }
    __syncthreads();

    if (tid == 0) {
        double t = 0.0;
        if (act0) {
            double t0 = 0.0;
#pragma unroll
            for (int x = 0; x < 8; x++) t0 += (double)wsum[0][x];
            double w0 = (ti == tj0) ? 1.0 : 2.0;
            double s0 = ((ti < TB / 2) == (tj0 < TB / 2)) ? 1.0 : -1.0;
            t += t0 * w0 * s0;
        }
        {
            double t1 = 0.0;
#pragma unroll
            for (int x = 0; x < 8; x++) t1 += (double)wsum[1][x];
            double w1 = (ti == tj1) ? 1.0 : 2.0;
            double s1 = ((ti < TB / 2) == (tj1 < TB / 2)) ? 1.0 : -1.0;
            t += t1 * w1 * s1;
        }
        g_part[bid] = t;
    }
}

// ---------------------------------------------------------------------------
// Kernel 3: fixed-order double reduction -> scalar
// ---------------------------------------------------------------------------
__global__ void __launch_bounds__(512) finish_kernel(float* out) {
    __shared__ double s[512];
    const int tid = threadIdx.x;
    const double2* p2 = (const double2*)g_part;       // NBLK2 even
    double t0 = 0.0, t1 = 0.0;
#pragma unroll 4
    for (int i = tid; i < NBLK2 / 2; i += 512) {
        double2 v = p2[i];
        t0 += v.x;
        t1 += v.y;
    }
    s[tid] = t0 + t1;
    __syncthreads();
#pragma unroll
    for (int off = 256; off; off >>= 1) {
        if (tid < off) s[tid] += s[tid + off];
        __syncthreads();
    }
    if (tid == 0) out[0] = (float)(s[0] / 67108864.0);   // / n^2, n = 8192
}

// ---------------------------------------------------------------------------
extern "C" void kernel_launch(void* const* d_in, const int* in_sizes, int n_in,
                              void* d_out, int out_size) {
    const float* src = (const float*)d_in[0];
    const float* tgt = (const float*)d_in[1];

    const int smem_bytes = 3 * ATILEB;     // 43008 B
    cudaFuncSetAttribute(pair_kernel, cudaFuncAttributeMaxDynamicSharedMemorySize,
                         smem_bytes);

    split_kernel<<<NP / 128, 128>>>(src, tgt);
    dim3 grid(NCJ, TB);
    pair_kernel<<<grid, 256, smem_bytes>>>();
    finish_kernel<<<1, 512>>>((float*)d_out);
}

// round 17
// speedup vs baseline: 1.5127x; 1.0777x over previous
#include <cuda_runtime.h>
#include <cuda_fp16.h>
#include <math.h>
#include <stdint.h>

// ---------------------------------------------------------------------------
// MMD^2 (RBF, gamma=1), 8192x16 fp32, via mma.sync.m16n8k16 fp16 (sm_100 base).
//
// Coords scaled by sqrt(2*log2e), split x = hi + lo (fp16) once in
// split_kernel. K = 48: A chunks [hi | lo | hi], B chunks [hi | hi | lo]
//   => acc = 2*log2e*dot(a,b)  (lo*lo dropped, ~2^-22 rel)
// Epilogue: k = ex2(acc) * ena * enb, ena/enb = exp2(-0.5|x_s|^2) per row.
// Each CTA (256 thr) computes a 128m x 512n super-tile: FOUR 128x128 tiles
// (ti, 4c..4c+3) sharing one A tile + A fragments. Warp tile 32m x 64n
// (the validated L1-optimal shape). Upper triangle only.
// ---------------------------------------------------------------------------

#define NSRC   8192
#define D      16
#define NP     16384
#define TILE   128
#define TB     (NP / TILE)                 // 128
#define NCJ    (TB / 4)                    // 32 column quads
#define NBLK4  (NCJ * TB)                  // 4096 CTAs
#define SQ2L   1.6986436004918308f         // sqrt(2*log2(e))
#define ROWB   112                         // 96B data + 16B pad (conflict-free)
#define NKC    3                           // K = 48, chunks of 16
#define ATILEB (TILE * ROWB)               // 14336 B per 128-row tile

// per point: u0,u1 = hi(16 fp16), u2,u3 = lo
__device__ uint4  g_S[NP * 4];
__device__ float  g_N[NP];                 // -0.5*|x_s|^2
__device__ double g_part[NBLK4];

// ---------------- helpers ----------------
__device__ __forceinline__ float ex2(float x) {
    float r; asm("ex2.approx.f32 %0, %1;" : "=f"(r) : "f"(x)); return r;
}
__device__ __forceinline__ uint32_t smem_u32(const void* p) {
    uint32_t a;
    asm("{ .reg .u64 t; cvta.to.shared.u64 t, %1; cvt.u32.u64 %0, t; }"
        : "=r"(a) : "l"(p));
    return a;
}
__device__ __forceinline__ void ldsm4(uint32_t* r, uint32_t addr) {
    asm volatile("ldmatrix.sync.aligned.m8n8.x4.shared.b16 {%0,%1,%2,%3}, [%4];"
                 : "=r"(r[0]), "=r"(r[1]), "=r"(r[2]), "=r"(r[3]) : "r"(addr));
}
__device__ __forceinline__ void mma16816(float* c, const uint32_t* a,
                                         uint32_t b0, uint32_t b1) {
    asm volatile("mma.sync.aligned.m16n8k16.row.col.f32.f16.f16.f32 "
                 "{%0,%1,%2,%3}, {%4,%5,%6,%7}, {%8,%9}, {%0,%1,%2,%3};"
                 : "+f"(c[0]), "+f"(c[1]), "+f"(c[2]), "+f"(c[3])
                 : "r"(a[0]), "r"(a[1]), "r"(a[2]), "r"(a[3]), "r"(b0), "r"(b1));
}

// ---------------------------------------------------------------------------
// Kernel 1: scale, fp16 hi/lo split, norm term.
// ---------------------------------------------------------------------------
__global__ void __launch_bounds__(128) split_kernel(const float* __restrict__ src,
                                                    const float* __restrict__ tgt) {
    int p = blockIdx.x * 128 + threadIdx.x;
    if (p >= NP) return;
    const float* x = (p < NSRC) ? (src + (size_t)p * D) : (tgt + (size_t)(p - NSRC) * D);

    uint4 u[4];
    __half* hi = (__half*)&u[0];
    __half* lo = (__half*)&u[2];

    float ns = 0.f;
#pragma unroll
    for (int d = 0; d < D; d++) {
        float v = x[d] * SQ2L;
        ns = fmaf(v, v, ns);
        __half h = __float2half_rn(v);
        hi[d] = h;
        lo[d] = __float2half_rn(v - __half2float(h));
    }
    uint4* out = g_S + (size_t)p * 4;
#pragma unroll
    for (int i = 0; i < 4; i++) out[i] = u[i];
    g_N[p] = -0.5f * ns;
}

// ---------------------------------------------------------------------------
// Kernel 2: 128x512 super-tile per CTA (four 128x128 tiles sharing A).
// blockIdx = (c, ti); tj = 4c + half; skip halves with tj < ti.
// Warp w: rows (w&3)*32 + {0,16}, cols (w>>2)*64 within each half.
// ---------------------------------------------------------------------------
__global__ void __launch_bounds__(256, 2) pair_kernel() {
    extern __shared__ __align__(16) char dsm[];
    __shared__ float sLA[TILE];
    __shared__ float sLB[4 * TILE];
    __shared__ float wsum[4][8];

    const int tid  = threadIdx.x;
    const int lane = tid & 31;
    const int w    = tid >> 5;

    const int ti   = blockIdx.y;
    const int tjb  = 4 * blockIdx.x;      // first tj of the quad
    const int bid  = blockIdx.y * NCJ + blockIdx.x;

    if (tjb + 3 < ti) {                   // whole quad below diagonal
        if (tid == 0) g_part[bid] = 0.0;
        return;
    }

    // ---- build A (rows 0..127) and B0..B3 (rows 128..639) ----
    for (int r = tid; r < 640; r += 256) {
        const int grp = r >> 7;           // 0=A, 1..4=B half grp-1
        const int row = r & 127;
        if (grp > 0 && tjb + (grp - 1) < ti) continue;
        const int tt = (grp == 0) ? ti : (tjb + grp - 1);
        const int pt = tt * TILE + row;
        const uint4* srow = g_S + (size_t)pt * 4;
        char* rbase = dsm + grp * ATILEB + row * ROWB;

        uint4 u[4];
#pragma unroll
        for (int i = 0; i < 4; i++) u[i] = srow[i];

        // A: [hi hi lo lo hi hi]    B: [hi hi hi hi lo lo]
        const int mapA[6] = {0,1, 2,3, 0,1};
        const int mapB[6] = {0,1, 0,1, 2,3};
#pragma unroll
        for (int c = 0; c < 6; c++) {
            int s = (grp == 0) ? mapA[c] : mapB[c];
            *(uint4*)(rbase + c * 16) = u[s];
        }
        float e = ex2(g_N[pt]);
        if (grp == 0) sLA[row] = e;
        else          sLB[(grp - 1) * TILE + row] = e;
    }
    __syncthreads();

    const uint32_t sA = smem_u32(dsm);
    const int mbase = (w & 3) * 32;
    const int nbase = (w >> 2) * 64;
    const int gid = lane >> 2;
    const int tig = lane & 3;

    // ---- preload A fragments ONCE (3 kc x 2 m-tiles = 24 regs) ----
    const uint32_t aRow   = (uint32_t)(mbase + (lane & 7) + ((lane >> 3) & 1) * 8);
    const uint32_t aAddr0 = sA + aRow * ROWB + ((lane >> 4) & 1) * 16;
    const uint32_t aAddr1 = aAddr0 + 16 * ROWB;
    uint32_t a0[NKC][4], a1[NKC][4];
#pragma unroll
    for (int kc = 0; kc < NKC; kc++) {
        ldsm4(a0[kc], aAddr0 + kc * 32);
        ldsm4(a1[kc], aAddr1 + kc * 32);
    }

    float ena[2][2];
#pragma unroll
    for (int mt = 0; mt < 2; mt++)
#pragma unroll
        for (int h = 0; h < 2; h++)
            ena[mt][h] = sLA[mbase + mt * 16 + gid + h * 8];

    const uint32_t bRowQ = (uint32_t)((lane & 7) + ((lane >> 4) & 1) * 8);
    const uint32_t bColH = ((lane >> 3) & 1) * 16;

    // ================= four sequential halves =================
#pragma unroll 1
    for (int half = 0; half < 4; half++) {
        if (tjb + half < ti) {
            if (lane == 0) wsum[half][w] = 0.f;
            continue;
        }
        const uint32_t sB = sA + (1 + half) * ATILEB;
        uint32_t bAddr[4];
#pragma unroll
        for (int q = 0; q < 4; q++)
            bAddr[q] = sB + (uint32_t)(nbase + 16 * q + bRowQ) * ROWB + bColH;

        float acc[2][8][4];
#pragma unroll
        for (int mt = 0; mt < 2; mt++)
#pragma unroll
            for (int nt = 0; nt < 8; nt++)
#pragma unroll
                for (int e = 0; e < 4; e++) acc[mt][nt][e] = 0.f;

#pragma unroll
        for (int kc = 0; kc < NKC; kc++) {
            const uint32_t ko = kc * 32;
            uint32_t b[4][4];
#pragma unroll
            for (int q = 0; q < 4; q++) ldsm4(b[q], bAddr[q] + ko);
#pragma unroll
            for (int nt = 0; nt < 8; nt++) {
                const uint32_t b0 = b[nt >> 1][(nt & 1) * 2];
                const uint32_t b1 = b[nt >> 1][(nt & 1) * 2 + 1];
                mma16816(acc[0][nt], a0[kc], b0, b1);
                mma16816(acc[1][nt], a1[kc], b0, b1);
            }
        }

        // ---- epilogue: k = ex2(acc) * ena * enb ----
        const float* lb = sLB + half * TILE;
        float enb[8][2];
#pragma unroll
        for (int nt = 0; nt < 8; nt++) {
            int j0 = nbase + nt * 8 + tig * 2;
            enb[nt][0] = lb[j0];
            enb[nt][1] = lb[j0 + 1];
        }

        float p[2][2] = {{0.f, 0.f}, {0.f, 0.f}};
#pragma unroll
        for (int mt = 0; mt < 2; mt++)
#pragma unroll
            for (int nt = 0; nt < 8; nt++)
#pragma unroll
                for (int e = 0; e < 4; e++)
                    p[mt][e >> 1] = fmaf(ex2(acc[mt][nt][e]), enb[nt][e & 1],
                                         p[mt][e >> 1]);

        float tsum = 0.f;
#pragma unroll
        for (int mt = 0; mt < 2; mt++)
#pragma unroll
            for (int h = 0; h < 2; h++)
                tsum = fmaf(p[mt][h], ena[mt][h], tsum);

#pragma unroll
        for (int off = 16; off; off >>= 1)
            tsum += __shfl_xor_sync(0xffffffffu, tsum, off);
        if (lane == 0) wsum[half][w] = tsum;
    }
    __syncthreads();

    if (tid == 0) {
        double t = 0.0;
#pragma unroll
        for (int half = 0; half < 4; half++) {
            const int tj = tjb + half;
            if (tj < ti) continue;
            double th = 0.0;
#pragma unroll
            for (int x = 0; x < 8; x++) th += (double)wsum[half][x];
            double wgt = (ti == tj) ? 1.0 : 2.0;
            double sgn = ((ti < TB / 2) == (tj < TB / 2)) ? 1.0 : -1.0;
            t += th * wgt * sgn;
        }
        g_part[bid] = t;
    }
}

// ---------------------------------------------------------------------------
// Kernel 3: fixed-order double reduction -> scalar
// ---------------------------------------------------------------------------
__global__ void __launch_bounds__(512) finish_kernel(float* out) {
    __shared__ double s[512];
    const int tid = threadIdx.x;
    const double2* p2 = (const double2*)g_part;       // NBLK4 even
    double t0 = 0.0, t1 = 0.0;
#pragma unroll 4
    for (int i = tid; i < NBLK4 / 2; i += 512) {
        double2 v = p2[i];
        t0 += v.x;
        t1 += v.y;
    }
    s[tid] = t0 + t1;
    __syncthreads();
#pragma unroll
    for (int off = 256; off; off >>= 1) {
        if (tid < off) s[tid] += s[tid + off];
        __syncthreads();
    }
    if (tid == 0) out[0] = (float)(s[0] / 67108864.0);   // / n^2, n = 8192
}

// ---------------------------------------------------------------------------
extern "C" void kernel_launch(void* const* d_in, const int* in_sizes, int n_in,
                              void* d_out, int out_size) {
    const float* src = (const float*)d_in[0];
    const float* tgt = (const float*)d_in[1];

    const int smem_bytes = 5 * ATILEB;     // 71680 B
    cudaFuncSetAttribute(pair_kernel, cudaFuncAttributeMaxDynamicSharedMemorySize,
                         smem_bytes);

    split_kernel<<<NP / 128, 128>>>(src, tgt);
    dim3 grid(NCJ, TB);
    pair_kernel<<<grid, 256, smem_bytes>>>();
    finish_kernel<<<1, 512>>>((float*)d_out);
}